// round 3
// baseline (speedup 1.0000x reference)
#include <cuda_runtime.h>
#include <math.h>

// Problem constants
#define BATCH 4
#define SEQ   2048
#define DM    1024
#define NH    16
#define HD    64
#define NTOK  (BATCH * SEQ)   // 8192
#define LN_EPS 1e-6f

// ---------------------------------------------------------------------------
// Scratch (device globals: no allocation allowed in kernel_launch)
// ---------------------------------------------------------------------------
__device__ float g_q[NTOK * DM];     // [B,H,S,HD]
__device__ float g_k[NTOK * DM];     // [B,H,S,HD]
__device__ float g_v[NTOK * DM];     // [B,H,S,HD]
__device__ float g_attn[NTOK * DM];  // [B,S,DM]
__device__ float g_proj[NTOK * DM];  // [B,S,DM]

// ---------------------------------------------------------------------------
// SGEMM: C[M=8192, N=1024] = A[8192,1024] @ W[1024,1024] + bias
// 128x128 tile, BK=8, 256 threads, 8x8 register blocking.
// SPLIT=1: write C into [B,H,S,HD] head-split layout. SPLIT=0: row-major.
// ---------------------------------------------------------------------------
#define GBM 128
#define GBN 128
#define GBK 8
#define AS_STRIDE 132   // pad to avoid STS bank conflicts

template <int SPLIT>
__global__ __launch_bounds__(256) void gemm128(
    const float* __restrict__ A, const float* __restrict__ W,
    const float* __restrict__ bias, float* __restrict__ C)
{
    __shared__ float As[GBK * AS_STRIDE];  // stored [k][m]
    __shared__ float Bs[GBK * AS_STRIDE];  // stored [k][n]

    const int tid = threadIdx.x;
    const int tx = tid & 15;       // 0..15 -> n
    const int ty = tid >> 4;       // 0..15 -> m
    const int row0 = blockIdx.y * GBM;
    const int col0 = blockIdx.x * GBN;

    // A tile global load mapping: thread -> (row, 4 consecutive k)
    const int a_row = tid >> 1;            // 0..127
    const int a_k   = (tid & 1) * 4;       // 0 or 4
    // B tile: thread -> (k row, 4 consecutive n)
    const int b_k   = tid >> 5;            // 0..7
    const int b_n   = (tid & 31) * 4;      // 0..124

    float acc[8][8];
    #pragma unroll
    for (int i = 0; i < 8; i++)
        #pragma unroll
        for (int j = 0; j < 8; j++) acc[i][j] = 0.0f;

    for (int k0 = 0; k0 < DM; k0 += GBK) {
        float4 a4 = *(const float4*)(A + (size_t)(row0 + a_row) * DM + k0 + a_k);
        As[(a_k + 0) * AS_STRIDE + a_row] = a4.x;
        As[(a_k + 1) * AS_STRIDE + a_row] = a4.y;
        As[(a_k + 2) * AS_STRIDE + a_row] = a4.z;
        As[(a_k + 3) * AS_STRIDE + a_row] = a4.w;
        *(float4*)(&Bs[b_k * AS_STRIDE + b_n]) =
            *(const float4*)(W + (size_t)(k0 + b_k) * DM + col0 + b_n);
        __syncthreads();

        #pragma unroll
        for (int k = 0; k < GBK; k++) {
            float a[8], b[8];
            *(float4*)(a)     = *(float4*)(&As[k * AS_STRIDE + ty * 8]);
            *(float4*)(a + 4) = *(float4*)(&As[k * AS_STRIDE + ty * 8 + 4]);
            *(float4*)(b)     = *(float4*)(&Bs[k * AS_STRIDE + tx * 8]);
            *(float4*)(b + 4) = *(float4*)(&Bs[k * AS_STRIDE + tx * 8 + 4]);
            #pragma unroll
            for (int i = 0; i < 8; i++)
                #pragma unroll
                for (int j = 0; j < 8; j++)
                    acc[i][j] = fmaf(a[i], b[j], acc[i][j]);
        }
        __syncthreads();
    }

    // Epilogue
    #pragma unroll
    for (int i = 0; i < 8; i++) {
        const int r = row0 + ty * 8 + i;
        const int bb = r / SEQ, ss = r % SEQ;
        #pragma unroll
        for (int j = 0; j < 8; j++) {
            const int c = col0 + tx * 8 + j;
            const float val = acc[i][j] + bias[c];
            if (SPLIT) {
                const int h = c >> 6, d = c & 63;
                C[(((size_t)(bb * NH + h) * SEQ) + ss) * HD + d] = val;
            } else {
                C[(size_t)r * DM + c] = val;
            }
        }
    }
}

// ---------------------------------------------------------------------------
// Flash attention: one block per (head-batch, 64-query tile).
// 256 threads: row = tid/4 (0..63 query rows), cg = tid%4 (16-col segment).
// Online softmax, fp32, K/V streamed through smem in 64-row tiles.
// ---------------------------------------------------------------------------
#define TS 64
#define TPAD 68
#define ATTN_SMEM (4 * TS * TPAD * (int)sizeof(float))  // Qs,Ks,Vs,Ps = 69632 B

__global__ __launch_bounds__(256) void attn_kernel(
    const float* __restrict__ Q, const float* __restrict__ K,
    const float* __restrict__ V, float* __restrict__ Out)
{
    extern __shared__ float smem[];
    float* Qs = smem;                 // [TS][TPAD]
    float* Ks = Qs + TS * TPAD;
    float* Vs = Ks + TS * TPAD;
    float* Ps = Vs + TS * TPAD;

    const int bh = blockIdx.y;            // 0..63
    const int b = bh / NH, h = bh % NH;
    const int q0 = blockIdx.x * TS;
    const float* Qb = Q + (size_t)bh * SEQ * HD;
    const float* Kb = K + (size_t)bh * SEQ * HD;
    const float* Vb = V + (size_t)bh * SEQ * HD;

    const int tid = threadIdx.x;
    const int row = tid >> 2;     // 0..63
    const int cg  = tid & 3;      // 0..3

    // Load Q tile (64x64 floats, as float4)
    for (int i = tid; i < TS * (HD / 4); i += 256) {
        const int r = i >> 4, c4 = (i & 15) * 4;
        *(float4*)&Qs[r * TPAD + c4] = *(const float4*)(Qb + (size_t)(q0 + r) * HD + c4);
    }

    float m = -1e30f, l = 0.0f;
    float o[16];
    #pragma unroll
    for (int i = 0; i < 16; i++) o[i] = 0.0f;

    for (int kv0 = 0; kv0 < SEQ; kv0 += TS) {
        __syncthreads();  // protect Ks/Vs from readers of previous tile
        for (int i = tid; i < TS * (HD / 4); i += 256) {
            const int r = i >> 4, c4 = (i & 15) * 4;
            *(float4*)&Ks[r * TPAD + c4] = *(const float4*)(Kb + (size_t)(kv0 + r) * HD + c4);
            *(float4*)&Vs[r * TPAD + c4] = *(const float4*)(Vb + (size_t)(kv0 + r) * HD + c4);
        }
        __syncthreads();

        // Scores for this thread's 16 kv columns
        float sc[16];
        #pragma unroll
        for (int jj = 0; jj < 16; jj++) {
            const int j = cg * 16 + jj;
            float4 a = make_float4(0.f, 0.f, 0.f, 0.f);
            #pragma unroll
            for (int d = 0; d < HD; d += 4) {
                float4 q4 = *(float4*)&Qs[row * TPAD + d];
                float4 k4 = *(float4*)&Ks[j * TPAD + d];
                a.x = fmaf(q4.x, k4.x, a.x);
                a.y = fmaf(q4.y, k4.y, a.y);
                a.z = fmaf(q4.z, k4.z, a.z);
                a.w = fmaf(q4.w, k4.w, a.w);
            }
            sc[jj] = (a.x + a.y + a.z + a.w) * 0.125f;  // 1/sqrt(64)
        }

        // Row max (16 local + shuffle among the 4 threads of this row)
        float mloc = sc[0];
        #pragma unroll
        for (int jj = 1; jj < 16; jj++) mloc = fmaxf(mloc, sc[jj]);
        mloc = fmaxf(mloc, __shfl_xor_sync(0xffffffffu, mloc, 1));
        mloc = fmaxf(mloc, __shfl_xor_sync(0xffffffffu, mloc, 2));
        const float mnew = fmaxf(m, mloc);
        const float corr = __expf(m - mnew);

        float psum = 0.0f;
        #pragma unroll
        for (int jj = 0; jj < 16; jj++) {
            const float p = __expf(sc[jj] - mnew);
            psum += p;
            Ps[row * TPAD + cg * 16 + jj] = p;
        }
        psum += __shfl_xor_sync(0xffffffffu, psum, 1);
        psum += __shfl_xor_sync(0xffffffffu, psum, 2);
        l = l * corr + psum;
        m = mnew;

        #pragma unroll
        for (int i = 0; i < 16; i++) o[i] *= corr;

        __syncwarp();  // Ps row is produced/consumed by the same 4 lanes (same warp)

        // O += P @ V over this tile (thread owns 16 depth cols: cg*16..)
        #pragma unroll
        for (int j = 0; j < TS; j++) {
            const float p = Ps[row * TPAD + j];
            #pragma unroll
            for (int d4 = 0; d4 < 4; d4++) {
                float4 v4 = *(float4*)&Vs[j * TPAD + cg * 16 + d4 * 4];
                o[d4 * 4 + 0] = fmaf(p, v4.x, o[d4 * 4 + 0]);
                o[d4 * 4 + 1] = fmaf(p, v4.y, o[d4 * 4 + 1]);
                o[d4 * 4 + 2] = fmaf(p, v4.z, o[d4 * 4 + 2]);
                o[d4 * 4 + 3] = fmaf(p, v4.w, o[d4 * 4 + 3]);
            }
        }
        __syncwarp();
    }

    const float inv = 1.0f / l;
    float* op = Out + ((size_t)(b * SEQ + q0 + row)) * DM + h * HD + cg * 16;
    #pragma unroll
    for (int d4 = 0; d4 < 4; d4++) {
        float4 r;
        r.x = o[d4 * 4 + 0] * inv;
        r.y = o[d4 * 4 + 1] * inv;
        r.z = o[d4 * 4 + 2] * inv;
        r.w = o[d4 * 4 + 3] * inv;
        *(float4*)(op + d4 * 4) = r;
    }
}

// ---------------------------------------------------------------------------
// Residual + LayerNorm: one block (256 threads) per token row; 4 floats/thread
// ---------------------------------------------------------------------------
__global__ __launch_bounds__(256) void ln_kernel(
    const float* __restrict__ X, const float* __restrict__ P,
    const float* __restrict__ gamma, const float* __restrict__ beta,
    float* __restrict__ out)
{
    const int r = blockIdx.x;
    const int t = threadIdx.x;
    const float4 x4 = ((const float4*)(X + (size_t)r * DM))[t];
    const float4 p4 = ((const float4*)(P + (size_t)r * DM))[t];
    float v0 = x4.x + p4.x, v1 = x4.y + p4.y, v2 = x4.z + p4.z, v3 = x4.w + p4.w;

    __shared__ float red[8];
    __shared__ float s_mu, s_rstd;

    // mean
    float s = v0 + v1 + v2 + v3;
    #pragma unroll
    for (int off = 16; off > 0; off >>= 1) s += __shfl_xor_sync(0xffffffffu, s, off);
    if ((t & 31) == 0) red[t >> 5] = s;
    __syncthreads();
    if (t == 0) {
        float tot = 0.f;
        #pragma unroll
        for (int i = 0; i < 8; i++) tot += red[i];
        s_mu = tot * (1.0f / DM);
    }
    __syncthreads();
    const float mu = s_mu;

    // variance
    float c0 = v0 - mu, c1 = v1 - mu, c2 = v2 - mu, c3 = v3 - mu;
    float sq = c0 * c0 + c1 * c1 + c2 * c2 + c3 * c3;
    #pragma unroll
    for (int off = 16; off > 0; off >>= 1) sq += __shfl_xor_sync(0xffffffffu, sq, off);
    if ((t & 31) == 0) red[t >> 5] = sq;
    __syncthreads();
    if (t == 0) {
        float tot = 0.f;
        #pragma unroll
        for (int i = 0; i < 8; i++) tot += red[i];
        s_rstd = rsqrtf(tot * (1.0f / DM) + LN_EPS);
    }
    __syncthreads();
    const float rstd = s_rstd;

    const float4 g4 = ((const float4*)gamma)[t];
    const float4 b4 = ((const float4*)beta)[t];
    float4 o4;
    o4.x = c0 * rstd * g4.x + b4.x;
    o4.y = c1 * rstd * g4.y + b4.y;
    o4.z = c2 * rstd * g4.z + b4.z;
    o4.w = c3 * rstd * g4.w + b4.w;
    ((float4*)(out + (size_t)r * DM))[t] = o4;
}

// ---------------------------------------------------------------------------
// Launch
// ---------------------------------------------------------------------------
extern "C" void kernel_launch(void* const* d_in, const int* in_sizes, int n_in,
                              void* d_out, int out_size)
{
    const float* x     = (const float*)d_in[0];
    const float* Wq    = (const float*)d_in[1];
    const float* bq    = (const float*)d_in[2];
    const float* Wk    = (const float*)d_in[3];
    const float* bk    = (const float*)d_in[4];
    const float* Wv    = (const float*)d_in[5];
    const float* bv    = (const float*)d_in[6];
    const float* Wo    = (const float*)d_in[7];
    const float* bo    = (const float*)d_in[8];
    const float* gamma = (const float*)d_in[9];
    const float* beta  = (const float*)d_in[10];
    float* out = (float*)d_out;

    float *q, *k, *v, *attn, *proj;
    cudaGetSymbolAddress((void**)&q,    g_q);
    cudaGetSymbolAddress((void**)&k,    g_k);
    cudaGetSymbolAddress((void**)&v,    g_v);
    cudaGetSymbolAddress((void**)&attn, g_attn);
    cudaGetSymbolAddress((void**)&proj, g_proj);

    dim3 ggrid(DM / GBN, NTOK / GBM);   // (8, 64)
    gemm128<1><<<ggrid, 256>>>(x, Wq, bq, q);
    gemm128<1><<<ggrid, 256>>>(x, Wk, bk, k);
    gemm128<1><<<ggrid, 256>>>(x, Wv, bv, v);

    cudaFuncSetAttribute(attn_kernel,
                         cudaFuncAttributeMaxDynamicSharedMemorySize, ATTN_SMEM);
    attn_kernel<<<dim3(SEQ / TS, BATCH * NH), 256, ATTN_SMEM>>>(q, k, v, attn);

    gemm128<0><<<ggrid, 256>>>(attn, Wo, bo, proj);

    ln_kernel<<<NTOK, 256>>>(x, proj, gamma, beta, out);
}